// round 7
// baseline (speedup 1.0000x reference)
#include <cuda_runtime.h>
#include <math.h>

#define BATCH 256
#define NNODE 184
#define HID   128
#define TH    24
#define TF    24
#define M_ROWS (BATCH*NNODE)      /* 47104 = 368*128 */
#define GCOLS  (3*HID)            /* 384 */

// ---------------- persistent device scratch ----------------
__device__ float g_hA[(size_t)M_ROWS*HID];
__device__ float g_hB[(size_t)M_ROWS*HID];
__device__ float g_xn[M_ROWS];
__device__ float g_x2[(size_t)M_ROWS*9];         // fore GRU input feats [f0..f7, g]
__device__ float g_comp1[NNODE*NNODE];
__device__ float g_comp2[NNODE*NNODE];
// Whh packed tf32 hi/lo in fragment-friendly order: [gatecol][kt*8 + pos],
// where pos pairs (2q,2q+1) hold k = (q, q+4) within each 8-wide k chunk.
__device__ float g_Bh_hi[GCOLS*HID], g_Bh_lo[GCOLS*HID];
__device__ float g_Bf_hi[GCOLS*HID], g_Bf_lo[GCOLS*HID];
__device__ float g_bih_h[GCOLS], g_bhh_h[GCOLS], g_W0_h[GCOLS], g_Wx_h[GCOLS];
__device__ float g_bih_f[GCOLS], g_bhh_f[GCOLS], g_W0_f[GCOLS], g_Wx_f[GCOLS*9];

__device__ __forceinline__ float sigf(float x)  { return 1.0f/(1.0f + __expf(-x)); }
__device__ __forceinline__ float tanhfast(float x){ return 2.0f/(1.0f + __expf(-2.0f*x)) - 1.0f; }
__device__ __forceinline__ unsigned f2tf32(float x) {
    unsigned r; asm("cvt.rna.tf32.f32 %0, %1;" : "=r"(r) : "f"(x)); return r;
}
__device__ __forceinline__ void mma4(float* d, const unsigned* a, const unsigned* b) {
    asm volatile("mma.sync.aligned.m16n8k8.row.col.f32.tf32.tf32.f32 "
        "{%0,%1,%2,%3}, {%4,%5,%6,%7}, {%8,%9}, {%0,%1,%2,%3};\n"
        : "+f"(d[0]), "+f"(d[1]), "+f"(d[2]), "+f"(d[3])
        : "r"(a[0]), "r"(a[1]), "r"(a[2]), "r"(a[3]), "r"(b[0]), "r"(b[1]));
}

// ---------------- prep ----------------
__global__ void prep_kernel(const float* __restrict__ angles,
                            const float* __restrict__ Whh_h, const float* __restrict__ Whh_f,
                            const float* __restrict__ Wih_h, const float* __restrict__ bih_h,
                            const float* __restrict__ bhh_h,
                            const float* __restrict__ Wih_f, const float* __restrict__ bih_f,
                            const float* __restrict__ bhh_f) {
    int i = blockIdx.x*blockDim.x + threadIdx.x;
    if (i < NNODE*NNODE) {
        float a = angles[i];
        g_comp1[i] = cosf(a);
        g_comp2[i] = cosf(a - 1.57079632679489662f);
    }
    if (i < GCOLS*HID) {
        int gc = i >> 7, k = i & 127;
        int kt = k >> 3, r = k & 7;
        int pos = kt*8 + ((r < 4) ? 2*r : 2*(r-4)+1);
        float wh = Whh_h[i];
        unsigned hb = f2tf32(wh);
        g_Bh_hi[gc*128+pos] = __uint_as_float(hb);
        g_Bh_lo[gc*128+pos] = __uint_as_float(f2tf32(wh - __uint_as_float(hb)));
        float wf = Whh_f[i];
        unsigned fb = f2tf32(wf);
        g_Bf_hi[gc*128+pos] = __uint_as_float(fb);
        g_Bf_lo[gc*128+pos] = __uint_as_float(f2tf32(wf - __uint_as_float(fb)));
    }
    if (i < GCOLS) {
        g_bih_h[i] = bih_h[i]; g_bhh_h[i] = bhh_h[i];
        g_W0_h[i]  = Wih_h[i*2]; g_Wx_h[i] = Wih_h[i*2+1];
        g_bih_f[i] = bih_f[i]; g_bhh_f[i] = bhh_f[i];
        g_W0_f[i]  = Wih_f[i*10];
        for (int k = 0; k < 9; k++) g_Wx_f[i*9+k] = Wih_f[i*10+1+k];
    }
}

__global__ void zero_kernel() {
    int i = blockIdx.x*blockDim.x + threadIdx.x;
    if (i < M_ROWS*HID) g_hA[i] = 0.0f;
}

// ---------------- fused step: G = h@Whh^T (3x TF32 mma) + GRU gates + h update ------
// Grid (4 col-groups, 368 row-groups), 256 threads = 8 warps; warp = 16 rows x 96 cols.
// Block tile: 128 rows x 96 gate cols (= 32 hidden units x {r,z,n}).
#define SMEM_FLOATS (128*132 + 96*132*2 + 128*9 + 96*9 + 96*3 + 128)
#define SMEM_BYTES  (SMEM_FLOATS*4)

template<int NF>
__global__ __launch_bounds__(256) void fused_step(int par, int t, int xn_mode,
        const float* __restrict__ pm25,
        const float* __restrict__ fcw, const float* __restrict__ fcb) {
    extern __shared__ float sm[];
    float* sA   = sm;                   // [128][132] fp32 h rows
    float* sBhi = sA   + 128*132;       // [96][132] packed tf32 hi
    float* sBlo = sBhi + 96*132;        // [96][132] packed tf32 lo
    float* sX   = sBlo + 96*132;        // [128][NF] input feats
    float* sWx  = sX   + 128*9;         // [96][NF]
    float* sW0  = sWx  + 96*9;          // [96]
    float* sbih = sW0  + 96;
    float* sbhh = sbih + 96;
    float* sxn  = sbhh + 96;            // [128]

    const float* hin  = par ? g_hB : g_hA;
    float*       hout = par ? g_hA : g_hB;
    const float* Bhi = (NF==1) ? g_Bh_hi : g_Bf_hi;
    const float* Blo = (NF==1) ? g_Bh_lo : g_Bf_lo;
    const float* bih = (NF==1) ? g_bih_h : g_bih_f;
    const float* bhh = (NF==1) ? g_bhh_h : g_bhh_f;
    const float* Wx  = (NF==1) ? g_Wx_h  : g_Wx_f;
    const float* W0  = (NF==1) ? g_W0_h  : g_W0_f;

    const int tid  = threadIdx.x;
    const int cg   = blockIdx.x;              // hidden units [cg*32, cg*32+32)
    const int row0 = blockIdx.y * 128;

    // ---- stage A (fp32 h rows) ----
    for (int i = tid; i < 128*32; i += 256) {
        int r = i >> 5, f = (i & 31) << 2;
        *(float4*)(sA + r*132 + f) = *(const float4*)(hin + (size_t)(row0+r)*HID + f);
    }
    // ---- stage B (96 gate cols, packed hi/lo) ----
    for (int i = tid; i < 96*32; i += 256) {
        int c = i >> 5, f = (i & 31) << 2;
        int gcol = ((c >> 5) << 7) + (cg << 5) + (c & 31);
        *(float4*)(sBhi + c*132 + f) = *(const float4*)(Bhi + gcol*128 + f);
        *(float4*)(sBlo + c*132 + f) = *(const float4*)(Blo + gcol*128 + f);
    }
    if (tid < 96) {
        int c = tid;
        int gcol = ((c >> 5) << 7) + (cg << 5) + (c & 31);
        sbih[c] = bih[gcol]; sbhh[c] = bhh[gcol]; sW0[c] = W0[gcol];
#pragma unroll
        for (int k = 0; k < NF; k++) sWx[c*NF + k] = Wx[gcol*NF + k];
    }
    if (tid < 128) {
        int row = row0 + tid;
        if (NF == 1) {
            int b = row / NNODE, n = row - b*NNODE;
            sX[tid] = pm25[((size_t)b*TH + t)*NNODE + n];
        } else {
#pragma unroll
            for (int k = 0; k < 9; k++) sX[tid*9 + k] = g_x2[(size_t)row*9 + k];
        }
        if (xn_mode == 2) sxn[tid] = g_xn[row];
    }
    __syncthreads();

    // ---- mainloop: 3x TF32 mma ----
    const int lane = tid & 31, w = tid >> 5;
    const int g = lane >> 2, q = lane & 3;
    const int rbase = (w << 4) + g;

    float acc[48];
#pragma unroll
    for (int i = 0; i < 48; i++) acc[i] = 0.0f;

#pragma unroll 2
    for (int kt = 0; kt < 16; kt++) {
        float a0 = sA[ rbase   *132 + kt*8 + q];
        float a1 = sA[(rbase+8)*132 + kt*8 + q];
        float a2 = sA[ rbase   *132 + kt*8 + q + 4];
        float a3 = sA[(rbase+8)*132 + kt*8 + q + 4];
        unsigned ah[4], al[4];
        ah[0]=f2tf32(a0); al[0]=f2tf32(a0-__uint_as_float(ah[0]));
        ah[1]=f2tf32(a1); al[1]=f2tf32(a1-__uint_as_float(ah[1]));
        ah[2]=f2tf32(a2); al[2]=f2tf32(a2-__uint_as_float(ah[2]));
        ah[3]=f2tf32(a3); al[3]=f2tf32(a3-__uint_as_float(ah[3]));
#pragma unroll
        for (int jn = 0; jn < 12; jn++) {
            float2 bh = *(const float2*)(sBhi + (8*jn + g)*132 + kt*8 + 2*q);
            float2 bl = *(const float2*)(sBlo + (8*jn + g)*132 + kt*8 + 2*q);
            unsigned bhu[2] = { __float_as_uint(bh.x), __float_as_uint(bh.y) };
            unsigned blu[2] = { __float_as_uint(bl.x), __float_as_uint(bl.y) };
            mma4(acc + jn*4, ah, bhu);   // hi*hi
            mma4(acc + jn*4, al, bhu);   // lo*hi
            mma4(acc + jn*4, ah, blu);   // hi*lo
        }
    }

    // ---- xn from sA if requested (hist steps t>=1) ----
    if (xn_mode == 1 && tid < 128) {
        float s = 0.0f;
#pragma unroll 8
        for (int k = 0; k < 128; k++) s += sA[tid*132 + k] * fcw[k];
        sxn[tid] = s + fcb[0];
    }
    __syncthreads();

    // ---- epilogue: gates + h update ----
#pragma unroll
    for (int jn4 = 0; jn4 < 4; jn4++) {
#pragma unroll
        for (int e = 0; e < 2; e++) {
            int j = jn4*8 + 2*q + e;           // hidden unit within cg block
            float w0r = sW0[j], w0z = sW0[32+j], w0n = sW0[64+j];
            float bir = sbih[j], biz = sbih[32+j], bin = sbih[64+j];
            float bhr = sbhh[j], bhz = sbhh[32+j], bhn = sbhh[64+j];
#pragma unroll
            for (int rs = 0; rs < 2; rs++) {
                int rib = rbase + rs*8;
                int d   = rs*2 + e;
                float xnv = (xn_mode == 0) ? 0.0f : sxn[rib];
                float gir = bir + xnv*w0r;
                float giz = biz + xnv*w0z;
                float gin = bin + xnv*w0n;
#pragma unroll
                for (int k = 0; k < NF; k++) {
                    float xk = (NF == 1) ? sX[rib] : sX[rib*9 + k];
                    gir = fmaf(xk, sWx[j*NF + k],      gir);
                    giz = fmaf(xk, sWx[(32+j)*NF + k], giz);
                    gin = fmaf(xk, sWx[(64+j)*NF + k], gin);
                }
                float rr = sigf(gir + acc[ jn4   *4 + d] + bhr);
                float zz = sigf(giz + acc[(4+jn4)*4 + d] + bhz);
                float nn = tanhfast(gin + rr*(acc[(8+jn4)*4 + d] + bhn));
                int hu = (cg << 5) + j;
                float hold = sA[rib*132 + hu];
                hout[(size_t)(row0 + rib)*HID + hu] = (1.0f - zz)*nn + zz*hold;
            }
        }
    }
}

// ---------------- graph: xn + wind-gated ChebConv gate -> g_x2; writes pred[t-1] ----
__global__ __launch_bounds__(256) void graph_kernel(int t,
        const float* __restrict__ feature, const float* __restrict__ adj,
        const float* __restrict__ cw0, const float* __restrict__ cw1,
        const float* __restrict__ cb,
        const float* __restrict__ fcw, const float* __restrict__ fcb,
        float* __restrict__ out) {
    const float* hin = (t & 1) ? g_hB : g_hA;    // h_in of fore step t (global step 24+t)
    int b   = blockIdx.x;
    int tid = threadIdx.x;
    int wid = tid >> 5, lane = tid & 31;
    __shared__ float sx[NNODE][9];
    __shared__ float sdinv[NNODE];
    __shared__ float shneg[NNODE];
    __shared__ unsigned int sM[NNODE][6];

    const float* fb = feature + (((size_t)b*(TH+TF) + TH + t)*NNODE)*8;
    for (int i = tid; i < NNODE; i += 256) {
#pragma unroll
        for (int c = 0; c < 8; c++) sx[i][1+c] = fb[i*8 + c];
    }
    // xn = fc(h_in) per node; also write previous step's prediction
    for (int i = wid; i < NNODE; i += 8) {
        const float* h = hin + (size_t)(b*NNODE + i)*HID;
        float s = h[lane]*fcw[lane] + h[lane+32]*fcw[lane+32]
                + h[lane+64]*fcw[lane+64] + h[lane+96]*fcw[lane+96];
#pragma unroll
        for (int o = 16; o > 0; o >>= 1) s += __shfl_down_sync(0xffffffffu, s, o);
        if (lane == 0) {
            s += fcb[0];
            sx[i][0] = s;
            g_xn[b*NNODE + i] = s;
            if (t > 0) out[((size_t)b*TF + (t-1))*NNODE + i] = s;
        }
    }
    __syncthreads();

    // pass 1: per-source-node edge bitmask + degree
    for (int i = tid; i < NNODE; i += 256) {
        float u = sx[i][1];
        float v = sx[i][2];
        const float* c1 = g_comp1 + i*NNODE;
        const float* c2 = g_comp2 + i*NNODE;
        const float* ar = adj     + i*NNODE;
        int deg = 0;
        for (int qq = 0; qq < 6; qq++) {
            unsigned bits = 0;
            int jend = (qq == 5) ? (NNODE - 160) : 32;
            for (int jj = 0; jj < jend; jj++) {
                int j = qq*32 + jj;
                float w = u*c1[j] + v*c2[j];
                if (w >= 0.5f && ar[j] > 0.0f) { deg++; bits |= (1u << jj); }
            }
            sM[i][qq] = bits;
        }
        sdinv[i] = (deg > 0) ? (1.0f / sqrtf((float)deg)) : 0.0f;
        shneg[i] = (deg > 0) ? 0.0f : -1.0f;
    }
    __syncthreads();

    // pass 2: ChebConv y, gate g, write g_x2 = [f0..f7, g]
    for (int j = tid; j < NNODE; j += 256) {
        float y[9];
#pragma unroll
        for (int c = 0; c < 9; c++) y[c] = 0.0f;
        int qq = j >> 5, sh = j & 31;
        for (int i = 0; i < NNODE; i++) {
            float w = ((sM[i][qq] >> sh) & 1u) ? sdinv[i] : 0.0f;
#pragma unroll
            for (int c = 0; c < 9; c++) y[c] = fmaf(w, sx[i][c], y[c]);
        }
        float dj = sdinv[j], hn = shneg[j];
        float acc = cb[0];
#pragma unroll
        for (int c = 0; c < 9; c++) {
            float yc = fmaf(-dj, y[c], hn*sx[j][c]);
            acc += sx[j][c]*cw0[c] + yc*cw1[c];
        }
        float gte = sigf(acc);
        float* o = g_x2 + (size_t)(b*NNODE + j)*9;
#pragma unroll
        for (int c = 0; c < 8; c++) o[c] = sx[j][1+c];
        o[8] = gte;
    }
}

// ---------------- final prediction (t = TF-1) from final h (in g_hA) ----------------
__global__ __launch_bounds__(256) void pred_kernel(const float* __restrict__ fcw,
                                                   const float* __restrict__ fcb,
                                                   float* __restrict__ out) {
    int wid = threadIdx.x >> 5, lane = threadIdx.x & 31;
    int row = blockIdx.x*8 + wid;
    const float* h = g_hA + (size_t)row*HID;
    float s = h[lane]*fcw[lane] + h[lane+32]*fcw[lane+32]
            + h[lane+64]*fcw[lane+64] + h[lane+96]*fcw[lane+96];
#pragma unroll
    for (int o = 16; o > 0; o >>= 1) s += __shfl_down_sync(0xffffffffu, s, o);
    if (lane == 0) {
        int b = row / NNODE, n = row - b*NNODE;
        out[((size_t)b*TF + (TF-1))*NNODE + n] = s + fcb[0];
    }
}

// ---------------- launch ----------------
extern "C" void kernel_launch(void* const* d_in, const int* in_sizes, int n_in,
                              void* d_out, int out_size) {
    const float* feature   = (const float*)d_in[0];
    const float* pm25      = (const float*)d_in[1];
    const float* adj       = (const float*)d_in[2];
    const float* angles    = (const float*)d_in[3];
    const float* W_ih_hist = (const float*)d_in[4];
    const float* W_hh_hist = (const float*)d_in[5];
    const float* b_ih_hist = (const float*)d_in[6];
    const float* b_hh_hist = (const float*)d_in[7];
    const float* fc_hist_w = (const float*)d_in[8];
    const float* fc_hist_b = (const float*)d_in[9];
    const float* cheb_w0   = (const float*)d_in[10];
    const float* cheb_w1   = (const float*)d_in[11];
    const float* cheb_b    = (const float*)d_in[12];
    const float* W_ih      = (const float*)d_in[13];
    const float* W_hh      = (const float*)d_in[14];
    const float* b_ih      = (const float*)d_in[15];
    const float* b_hh      = (const float*)d_in[16];
    const float* fc_out_w  = (const float*)d_in[17];
    const float* fc_out_b  = (const float*)d_in[18];
    float* out = (float*)d_out;

    cudaFuncSetAttribute(fused_step<1>, cudaFuncAttributeMaxDynamicSharedMemorySize, SMEM_BYTES);
    cudaFuncSetAttribute(fused_step<9>, cudaFuncAttributeMaxDynamicSharedMemorySize, SMEM_BYTES);

    prep_kernel<<<(GCOLS*HID + 255)/256, 256>>>(angles, W_hh_hist, W_hh,
                                                W_ih_hist, b_ih_hist, b_hh_hist,
                                                W_ih, b_ih, b_hh);
    zero_kernel<<<(M_ROWS*HID + 255)/256, 256>>>();

    dim3 fgrid(4, M_ROWS/128);   // (4, 368)

    for (int t = 0; t < TH; t++) {
        int s = t;
        fused_step<1><<<fgrid, 256, SMEM_BYTES>>>(s & 1, t, (t == 0) ? 0 : 1,
                                                  pm25, fc_hist_w, fc_hist_b);
    }
    for (int t = 0; t < TF; t++) {
        int s = TH + t;
        const float* fw = (t == 0) ? fc_hist_w : fc_out_w;
        const float* fb = (t == 0) ? fc_hist_b : fc_out_b;
        graph_kernel<<<BATCH, 256>>>(t, feature, adj, cheb_w0, cheb_w1, cheb_b,
                                     fw, fb, out);
        fused_step<9><<<fgrid, 256, SMEM_BYTES>>>(s & 1, t, 2,
                                                  pm25, fw, fb);
    }
    pred_kernel<<<M_ROWS/8, 256>>>(fc_out_w, fc_out_b, out);
}

// round 8
// speedup vs baseline: 1.7033x; 1.7033x over previous
#include <cuda_runtime.h>
#include <math.h>

#define BATCH 256
#define NNODE 184
#define HID   128
#define TH    24
#define TF    24
#define M_ROWS (BATCH*NNODE)      /* 47104 = 368*128 */
#define GCOLS  (3*HID)            /* 384 */

// ---------------- persistent device scratch ----------------
__device__ float g_hA[(size_t)M_ROWS*HID];
__device__ float g_hB[(size_t)M_ROWS*HID];
__device__ float g_xn[M_ROWS];
__device__ float g_xnpart[4*M_ROWS];             // per-colgroup fc partial sums
__device__ float g_x2[(size_t)M_ROWS*9];         // fore GRU input feats [f0..f7, g]
__device__ float g_comp1[NNODE*NNODE];
__device__ float g_comp2[NNODE*NNODE];
// Whh packed as bf16(hi,lo) words, [gatecol][k] with k permuted so that within
// each 8-k chunk, real k r<4 -> slot 2r, r>=4 -> slot 2(r-4)+1 (makes the
// (q, q+4) fragment pair adjacent -> one LDS.64).
__device__ float g_Bh[GCOLS*HID];
__device__ float g_Bf[GCOLS*HID];
__device__ float g_bih_h[GCOLS], g_bhh_h[GCOLS], g_W0_h[GCOLS], g_Wx_h[GCOLS];
__device__ float g_bih_f[GCOLS], g_bhh_f[GCOLS], g_W0_f[GCOLS], g_Wx_f[GCOLS*9];

__device__ __forceinline__ float sigf(float x)   { return 1.0f/(1.0f + __expf(-x)); }
__device__ __forceinline__ float tanhfast(float x){ return 2.0f/(1.0f + __expf(-2.0f*x)) - 1.0f; }

// pack x into (low16 = bf16(x), high16 = bf16(x - float(bf16(x))))
__device__ __forceinline__ unsigned pack_hl(float x) {
    unsigned h2; asm("cvt.rn.bf16x2.f32 %0, %1, %2;" : "=r"(h2) : "f"(x), "f"(x));
    float hif = __uint_as_float(h2 << 16);
    float lo  = x - hif;
    unsigned w; asm("cvt.rn.bf16x2.f32 %0, %1, %2;" : "=r"(w) : "f"(lo), "f"(x));
    return w;
}

__device__ __forceinline__ void mma_bf16(float* d, const unsigned* a, unsigned b0, unsigned b1) {
    asm volatile("mma.sync.aligned.m16n8k16.row.col.f32.bf16.bf16.f32 "
        "{%0,%1,%2,%3}, {%4,%5,%6,%7}, {%8,%9}, {%0,%1,%2,%3};"
        : "+f"(d[0]), "+f"(d[1]), "+f"(d[2]), "+f"(d[3])
        : "r"(a[0]), "r"(a[1]), "r"(a[2]), "r"(a[3]), "r"(b0), "r"(b1));
}

// ---------------- prep ----------------
__global__ void prep_kernel(const float* __restrict__ angles,
                            const float* __restrict__ Whh_h, const float* __restrict__ Whh_f,
                            const float* __restrict__ Wih_h, const float* __restrict__ bih_h,
                            const float* __restrict__ bhh_h,
                            const float* __restrict__ Wih_f, const float* __restrict__ bih_f,
                            const float* __restrict__ bhh_f) {
    int i = blockIdx.x*blockDim.x + threadIdx.x;
    if (i < NNODE*NNODE) {
        float a = angles[i];
        g_comp1[i] = cosf(a);
        g_comp2[i] = cosf(a - 1.57079632679489662f);
    }
    if (i < GCOLS*HID) {
        int gc = i >> 7, k = i & 127;
        int kt = k >> 3, r = k & 7;
        int pos = kt*8 + ((r < 4) ? 2*r : 2*(r-4)+1);
        g_Bh[gc*128 + pos] = __uint_as_float(pack_hl(Whh_h[i]));
        g_Bf[gc*128 + pos] = __uint_as_float(pack_hl(Whh_f[i]));
    }
    if (i < GCOLS) {
        g_bih_h[i] = bih_h[i]; g_bhh_h[i] = bhh_h[i];
        g_W0_h[i]  = Wih_h[i*2]; g_Wx_h[i] = Wih_h[i*2+1];
        g_bih_f[i] = bih_f[i]; g_bhh_f[i] = bhh_f[i];
        g_W0_f[i]  = Wih_f[i*10];
        for (int k = 0; k < 9; k++) g_Wx_f[i*9+k] = Wih_f[i*10+1+k];
    }
}

__global__ void zero_kernel() {
    int i = blockIdx.x*blockDim.x + threadIdx.x;
    if (i < M_ROWS*HID) g_hA[i] = 0.0f;
}

// ---------------- fused step: G = h@Whh^T (bf16-split mma) + GRU gates ----------------
// Grid (4 col-groups, 368 row-groups), 256 threads = 8 warps; warp = 16 rows x 96 cols.
// Block tile: 128 rows x 96 gate cols (= 32 hidden units x {r,z,n}).
#define SB_STRIDE 136
#define SMEM_FLOATS (96*SB_STRIDE + 128*33 + 128*9 + 96*9 + 96*3 + 128 + 32)
#define SMEM_BYTES  (SMEM_FLOATS*4)

template<int NF>
__global__ __launch_bounds__(256, 2) void fused_step(int par, int t, int xn_mode,
        const float* __restrict__ pm25,
        const float* __restrict__ fcw, const float* __restrict__ fcb) {
    extern __shared__ float sm[];
    float* sB   = sm;                    // [96][136] packed bf16x2 words
    float* sAh  = sB  + 96*SB_STRIDE;    // [128][33] hold slice (this block's 32 hu)
    float* sX   = sAh + 128*33;          // [128][<=9] input feats
    float* sWx  = sX  + 128*9;           // [96][<=9]
    float* sW0  = sWx + 96*9;            // [96]
    float* sbih = sW0 + 96;
    float* sbhh = sbih + 96;
    float* sxn  = sbhh + 96;             // [128]
    float* sfcw = sxn + 128;             // [32]

    const float* hin  = par ? g_hB : g_hA;
    float*       hout = par ? g_hA : g_hB;
    const float* Bw  = (NF==1) ? g_Bh   : g_Bf;
    const float* bih = (NF==1) ? g_bih_h : g_bih_f;
    const float* bhh = (NF==1) ? g_bhh_h : g_bhh_f;
    const float* Wx  = (NF==1) ? g_Wx_h  : g_Wx_f;
    const float* W0  = (NF==1) ? g_W0_h  : g_W0_f;

    const int tid  = threadIdx.x;
    const int cg   = blockIdx.x;              // hidden units [cg*32, cg*32+32)
    const int row0 = blockIdx.y * 128;

    // ---- stage B (96 gate cols of packed words) ----
    for (int i = tid; i < 96*32; i += 256) {
        int c = i >> 5, f = (i & 31) << 2;
        int gcol = ((c >> 5) << 7) + (cg << 5) + (c & 31);
        *(float4*)(sB + c*SB_STRIDE + f) = *(const float4*)(Bw + gcol*128 + f);
    }
    // ---- stage hold slice ----
    for (int i = tid; i < 128*32; i += 256) {
        int r = i >> 5, c = i & 31;
        sAh[r*33 + c] = hin[(size_t)(row0+r)*HID + (cg<<5) + c];
    }
    if (tid < 96) {
        int gcol = ((tid >> 5) << 7) + (cg << 5) + (tid & 31);
        sbih[tid] = bih[gcol]; sbhh[tid] = bhh[gcol]; sW0[tid] = W0[gcol];
#pragma unroll
        for (int k = 0; k < NF; k++) sWx[tid*NF + k] = Wx[gcol*NF + k];
    }
    if (tid >= 96 && tid < 128) sfcw[tid-96] = fcw[(cg<<5) + (tid-96)];
    if (tid < 128) {
        int row = row0 + tid;
        if (NF == 1) {
            int b = row / NNODE, n = row - b*NNODE;
            sX[tid] = pm25[((size_t)b*TH + t)*NNODE + n];
        } else {
#pragma unroll
            for (int k = 0; k < 9; k++) sX[tid*9 + k] = g_x2[(size_t)row*9 + k];
        }
        if (xn_mode == 1) {
            float s = fcb[0];
#pragma unroll
            for (int c2 = 0; c2 < 4; c2++) s += g_xnpart[c2*M_ROWS + row];
            sxn[tid] = s;
        } else if (xn_mode == 2) {
            sxn[tid] = g_xn[row];
        }
    }
    __syncthreads();

    const int lane = tid & 31, w = tid >> 5;
    const int g = lane >> 2, q = lane & 3;
    const int rbase = (w << 4) + g;

    float acc[48];
#pragma unroll
    for (int i = 0; i < 48; i++) acc[i] = 0.0f;

    const float* pA0 = hin + (size_t)(row0 + rbase)*HID + q;
    const float* pA1 = pA0 + 8*HID;

    float an[4];
    an[0] = pA0[0]; an[1] = pA1[0]; an[2] = pA0[4]; an[3] = pA1[4];

#pragma unroll
    for (int kt = 0; kt < 16; kt++) {
        unsigned aw[4];
        aw[0] = pack_hl(an[0]); aw[1] = pack_hl(an[1]);
        aw[2] = pack_hl(an[2]); aw[3] = pack_hl(an[3]);
        if (kt < 15) {
            an[0] = pA0[(kt+1)*8];     an[1] = pA1[(kt+1)*8];
            an[2] = pA0[(kt+1)*8 + 4]; an[3] = pA1[(kt+1)*8 + 4];
        }
        const float* pb = sB + g*SB_STRIDE + kt*8 + 2*q;
#pragma unroll
        for (int jn = 0; jn < 12; jn++) {
            uint2 wb = *(const uint2*)(pb + jn*8*SB_STRIDE);
            unsigned bh0 = __byte_perm(wb.x, wb.x, 0x1010);  // (hi,hi)
            unsigned bh1 = __byte_perm(wb.y, wb.y, 0x1010);
            unsigned bl0 = __byte_perm(wb.x, 0,    0x4432);  // (lo, 0)
            unsigned bl1 = __byte_perm(wb.y, 0,    0x4432);
            mma_bf16(acc + jn*4, aw, bh0, bh1);   // a_hi*b_hi + a_lo*b_hi
            mma_bf16(acc + jn*4, aw, bl0, bl1);   // a_hi*b_lo
        }
    }

    // ---- epilogue: gates + h update + fc partials ----
    float p0 = 0.0f, p1 = 0.0f;
#pragma unroll
    for (int jn4 = 0; jn4 < 4; jn4++) {
#pragma unroll
        for (int e = 0; e < 2; e++) {
            int j = jn4*8 + 2*q + e;           // hidden unit within cg block
            float w0r = sW0[j], w0z = sW0[32+j], w0n = sW0[64+j];
            float bir = sbih[j], biz = sbih[32+j], bin = sbih[64+j];
            float bhr = sbhh[j], bhz = sbhh[32+j], bhn = sbhh[64+j];
            float fwj = sfcw[j];
#pragma unroll
            for (int rs = 0; rs < 2; rs++) {
                int rib = rbase + rs*8;
                int d   = rs*2 + e;
                float xnv = (xn_mode == 0) ? 0.0f : sxn[rib];
                float gir = bir + xnv*w0r;
                float giz = biz + xnv*w0z;
                float gin = bin + xnv*w0n;
#pragma unroll
                for (int k = 0; k < NF; k++) {
                    float xk = (NF == 1) ? sX[rib] : sX[rib*9 + k];
                    gir = fmaf(xk, sWx[j*NF + k],      gir);
                    giz = fmaf(xk, sWx[(32+j)*NF + k], giz);
                    gin = fmaf(xk, sWx[(64+j)*NF + k], gin);
                }
                float rr = sigf(gir + acc[ jn4   *4 + d] + bhr);
                float zz = sigf(giz + acc[(4+jn4)*4 + d] + bhz);
                float nn = tanhfast(gin + rr*(acc[(8+jn4)*4 + d] + bhn));
                float hold = sAh[rib*33 + j];
                float hnew = (1.0f - zz)*nn + zz*hold;
                hout[(size_t)(row0 + rib)*HID + (cg<<5) + j] = hnew;
                float c = hnew * fwj;
                if (rs == 0) p0 += c; else p1 += c;
            }
        }
    }
    // reduce partials over q (lanes g*4+q) and store
    p0 += __shfl_xor_sync(0xffffffffu, p0, 1);
    p0 += __shfl_xor_sync(0xffffffffu, p0, 2);
    p1 += __shfl_xor_sync(0xffffffffu, p1, 1);
    p1 += __shfl_xor_sync(0xffffffffu, p1, 2);
    if (q == 0) {
        g_xnpart[cg*M_ROWS + row0 + rbase]     = p0;
        g_xnpart[cg*M_ROWS + row0 + rbase + 8] = p1;
    }
}

// ---------------- graph: xn (from partials) + wind-gated ChebConv gate -> g_x2 ------
__global__ __launch_bounds__(256) void graph_kernel(int t,
        const float* __restrict__ feature, const float* __restrict__ adj,
        const float* __restrict__ cw0, const float* __restrict__ cw1,
        const float* __restrict__ cb, const float* __restrict__ fcb,
        float* __restrict__ out) {
    int b   = blockIdx.x;
    int tid = threadIdx.x;
    __shared__ float sx[NNODE][9];
    __shared__ float sdinv[NNODE];
    __shared__ float shneg[NNODE];
    __shared__ unsigned int sM[NNODE][6];

    const float* fb = feature + (((size_t)b*(TH+TF) + TH + t)*NNODE)*8;
    for (int i = tid; i < NNODE; i += 256) {
#pragma unroll
        for (int c = 0; c < 8; c++) sx[i][1+c] = fb[i*8 + c];
        int row = b*NNODE + i;
        float s = fcb[0] + g_xnpart[row] + g_xnpart[M_ROWS + row]
                + g_xnpart[2*M_ROWS + row] + g_xnpart[3*M_ROWS + row];
        sx[i][0] = s;
        g_xn[row] = s;
        if (t > 0) out[((size_t)b*TF + (t-1))*NNODE + i] = s;
    }
    __syncthreads();

    // pass 1: per-source-node edge bitmask + degree
    for (int i = tid; i < NNODE; i += 256) {
        float u = sx[i][1];
        float v = sx[i][2];
        const float* c1 = g_comp1 + i*NNODE;
        const float* c2 = g_comp2 + i*NNODE;
        const float* ar = adj     + i*NNODE;
        int deg = 0;
        for (int qq = 0; qq < 6; qq++) {
            unsigned bits = 0;
            int jend = (qq == 5) ? (NNODE - 160) : 32;
            for (int jj = 0; jj < jend; jj++) {
                int j = qq*32 + jj;
                float w = u*c1[j] + v*c2[j];
                if (w >= 0.5f && ar[j] > 0.0f) { deg++; bits |= (1u << jj); }
            }
            sM[i][qq] = bits;
        }
        sdinv[i] = (deg > 0) ? (1.0f / sqrtf((float)deg)) : 0.0f;
        shneg[i] = (deg > 0) ? 0.0f : -1.0f;
    }
    __syncthreads();

    // pass 2: ChebConv y, gate g, write g_x2 = [f0..f7, g]
    for (int j = tid; j < NNODE; j += 256) {
        float y[9];
#pragma unroll
        for (int c = 0; c < 9; c++) y[c] = 0.0f;
        int qq = j >> 5, sh = j & 31;
        for (int i = 0; i < NNODE; i++) {
            float w = ((sM[i][qq] >> sh) & 1u) ? sdinv[i] : 0.0f;
#pragma unroll
            for (int c = 0; c < 9; c++) y[c] = fmaf(w, sx[i][c], y[c]);
        }
        float dj = sdinv[j], hn = shneg[j];
        float acc = cb[0];
#pragma unroll
        for (int c = 0; c < 9; c++) {
            float yc = fmaf(-dj, y[c], hn*sx[j][c]);
            acc += sx[j][c]*cw0[c] + yc*cw1[c];
        }
        float gte = sigf(acc);
        float* o = g_x2 + (size_t)(b*NNODE + j)*9;
#pragma unroll
        for (int c = 0; c < 8; c++) o[c] = sx[j][1+c];
        o[8] = gte;
    }
}

// ---------------- final prediction (t = TF-1) from last partials ----------------
__global__ __launch_bounds__(256) void pred_kernel(const float* __restrict__ fcb,
                                                   float* __restrict__ out) {
    int row = blockIdx.x*256 + threadIdx.x;
    float s = fcb[0] + g_xnpart[row] + g_xnpart[M_ROWS + row]
            + g_xnpart[2*M_ROWS + row] + g_xnpart[3*M_ROWS + row];
    int b = row / NNODE, n = row - b*NNODE;
    out[((size_t)b*TF + (TF-1))*NNODE + n] = s;
}

// ---------------- launch ----------------
extern "C" void kernel_launch(void* const* d_in, const int* in_sizes, int n_in,
                              void* d_out, int out_size) {
    const float* feature   = (const float*)d_in[0];
    const float* pm25      = (const float*)d_in[1];
    const float* adj       = (const float*)d_in[2];
    const float* angles    = (const float*)d_in[3];
    const float* W_ih_hist = (const float*)d_in[4];
    const float* W_hh_hist = (const float*)d_in[5];
    const float* b_ih_hist = (const float*)d_in[6];
    const float* b_hh_hist = (const float*)d_in[7];
    const float* fc_hist_w = (const float*)d_in[8];
    const float* fc_hist_b = (const float*)d_in[9];
    const float* cheb_w0   = (const float*)d_in[10];
    const float* cheb_w1   = (const float*)d_in[11];
    const float* cheb_b    = (const float*)d_in[12];
    const float* W_ih      = (const float*)d_in[13];
    const float* W_hh      = (const float*)d_in[14];
    const float* b_ih      = (const float*)d_in[15];
    const float* b_hh      = (const float*)d_in[16];
    const float* fc_out_w  = (const float*)d_in[17];
    const float* fc_out_b  = (const float*)d_in[18];
    float* out = (float*)d_out;

    cudaFuncSetAttribute(fused_step<1>, cudaFuncAttributeMaxDynamicSharedMemorySize, SMEM_BYTES);
    cudaFuncSetAttribute(fused_step<9>, cudaFuncAttributeMaxDynamicSharedMemorySize, SMEM_BYTES);

    prep_kernel<<<(GCOLS*HID + 255)/256, 256>>>(angles, W_hh_hist, W_hh,
                                                W_ih_hist, b_ih_hist, b_hh_hist,
                                                W_ih, b_ih, b_hh);
    zero_kernel<<<(M_ROWS*HID + 255)/256, 256>>>();

    dim3 fgrid(4, M_ROWS/128);   // (4, 368)

    for (int t = 0; t < TH; t++) {
        fused_step<1><<<fgrid, 256, SMEM_BYTES>>>(t & 1, t, (t == 0) ? 0 : 1,
                                                  pm25, fc_hist_w, fc_hist_b);
    }
    for (int t = 0; t < TF; t++) {
        int s = TH + t;
        graph_kernel<<<BATCH, 256>>>(t, feature, adj, cheb_w0, cheb_w1, cheb_b,
                                     (t == 0) ? fc_hist_b : fc_out_b, out);
        fused_step<9><<<fgrid, 256, SMEM_BYTES>>>(s & 1, t, 2,
                                                  pm25, fc_out_w, fc_out_b);
    }
    pred_kernel<<<M_ROWS/256, 256>>>(fc_out_b, out);
}

// round 9
// speedup vs baseline: 1.7037x; 1.0002x over previous
#include <cuda_runtime.h>
#include <math.h>

#define BATCH 256
#define NNODE 184
#define HID   128
#define TH    24
#define TF    24
#define M_ROWS (BATCH*NNODE)      /* 47104 = 368*128 */
#define GCOLS  (3*HID)            /* 384 */

// ---------------- persistent device scratch ----------------
__device__ float g_hA[(size_t)M_ROWS*HID];
__device__ float g_hB[(size_t)M_ROWS*HID];
__device__ float g_xn[M_ROWS];
__device__ float g_xnpart[4*M_ROWS];             // per-colgroup fc partial sums
__device__ float g_x2[(size_t)M_ROWS*9];         // fore GRU input feats [f0..f7, g]
__device__ float g_comp1[NNODE*NNODE];
__device__ float g_comp2[NNODE*NNODE];
// Whh packed as bf16(hi,lo) words, [gatecol][k] with k permuted so that within
// each 8-k chunk, real k r<4 -> slot 2r, r>=4 -> slot 2(r-4)+1 (makes the
// (q, q+4) fragment pair adjacent -> one LDS.64).
__device__ float g_Bh[GCOLS*HID];
__device__ float g_Bf[GCOLS*HID];
__device__ float g_bih_h[GCOLS], g_bhh_h[GCOLS], g_W0_h[GCOLS], g_Wx_h[GCOLS];
__device__ float g_bih_f[GCOLS], g_bhh_f[GCOLS], g_W0_f[GCOLS], g_Wx_f[GCOLS*9];

__device__ __forceinline__ float sigf(float x)   { return 1.0f/(1.0f + __expf(-x)); }
__device__ __forceinline__ float tanhfast(float x){ return 2.0f/(1.0f + __expf(-2.0f*x)) - 1.0f; }

// pack x into (low16 = bf16(x), high16 = bf16(x - float(bf16(x))))
__device__ __forceinline__ unsigned pack_hl(float x) {
    unsigned h2; asm("cvt.rn.bf16x2.f32 %0, %1, %2;" : "=r"(h2) : "f"(x), "f"(x));
    float hif = __uint_as_float(h2 << 16);
    float lo  = x - hif;
    unsigned w; asm("cvt.rn.bf16x2.f32 %0, %1, %2;" : "=r"(w) : "f"(lo), "f"(x));
    return w;
}

__device__ __forceinline__ void mma_bf16(float* d, const unsigned* a, unsigned b0, unsigned b1) {
    asm volatile("mma.sync.aligned.m16n8k16.row.col.f32.bf16.bf16.f32 "
        "{%0,%1,%2,%3}, {%4,%5,%6,%7}, {%8,%9}, {%0,%1,%2,%3};"
        : "+f"(d[0]), "+f"(d[1]), "+f"(d[2]), "+f"(d[3])
        : "r"(a[0]), "r"(a[1]), "r"(a[2]), "r"(a[3]), "r"(b0), "r"(b1));
}

// ---------------- prep ----------------
__global__ void prep_kernel(const float* __restrict__ angles,
                            const float* __restrict__ Whh_h, const float* __restrict__ Whh_f,
                            const float* __restrict__ Wih_h, const float* __restrict__ bih_h,
                            const float* __restrict__ bhh_h,
                            const float* __restrict__ Wih_f, const float* __restrict__ bih_f,
                            const float* __restrict__ bhh_f) {
    int i = blockIdx.x*blockDim.x + threadIdx.x;
    if (i < NNODE*NNODE) {
        float a = angles[i];
        g_comp1[i] = cosf(a);
        g_comp2[i] = cosf(a - 1.57079632679489662f);
    }
    if (i < GCOLS*HID) {
        int gc = i >> 7, k = i & 127;
        int kt = k >> 3, r = k & 7;
        int pos = kt*8 + ((r < 4) ? 2*r : 2*(r-4)+1);
        g_Bh[gc*128 + pos] = __uint_as_float(pack_hl(Whh_h[i]));
        g_Bf[gc*128 + pos] = __uint_as_float(pack_hl(Whh_f[i]));
    }
    if (i < GCOLS) {
        g_bih_h[i] = bih_h[i]; g_bhh_h[i] = bhh_h[i];
        g_W0_h[i]  = Wih_h[i*2]; g_Wx_h[i] = Wih_h[i*2+1];
        g_bih_f[i] = bih_f[i]; g_bhh_f[i] = bhh_f[i];
        g_W0_f[i]  = Wih_f[i*10];
        for (int k = 0; k < 9; k++) g_Wx_f[i*9+k] = Wih_f[i*10+1+k];
    }
}

__global__ void zero_kernel() {
    int i = blockIdx.x*blockDim.x + threadIdx.x;
    if (i < M_ROWS*HID) g_hA[i] = 0.0f;
}

// ---------------- fused step: G = h@Whh^T (bf16-split mma) + GRU gates ----------------
// Grid (4 col-groups, 368 row-groups), 256 threads = 8 warps; warp = 16 rows x 96 cols.
// Block tile: 128 rows x 96 gate cols (= 32 hidden units x {r,z,n}).
#define SB_STRIDE 136
#define SMEM_FLOATS (96*SB_STRIDE + 128*33 + 128*9 + 96*9 + 96*3 + 128 + 32)
#define SMEM_BYTES  (SMEM_FLOATS*4)

template<int NF>
__global__ __launch_bounds__(256, 2) void fused_step(int par, int t, int xn_mode,
        const float* __restrict__ pm25,
        const float* __restrict__ fcw, const float* __restrict__ fcb) {
    extern __shared__ float sm[];
    float* sB   = sm;                    // [96][136] packed bf16x2 words
    float* sAh  = sB  + 96*SB_STRIDE;    // [128][33] hold slice (this block's 32 hu)
    float* sX   = sAh + 128*33;          // [128][<=9] input feats
    float* sWx  = sX  + 128*9;           // [96][<=9]
    float* sW0  = sWx + 96*9;            // [96]
    float* sbih = sW0 + 96;
    float* sbhh = sbih + 96;
    float* sxn  = sbhh + 96;             // [128]
    float* sfcw = sxn + 128;             // [32]

    const float* hin  = par ? g_hB : g_hA;
    float*       hout = par ? g_hA : g_hB;
    const float* Bw  = (NF==1) ? g_Bh   : g_Bf;
    const float* bih = (NF==1) ? g_bih_h : g_bih_f;
    const float* bhh = (NF==1) ? g_bhh_h : g_bhh_f;
    const float* Wx  = (NF==1) ? g_Wx_h  : g_Wx_f;
    const float* W0  = (NF==1) ? g_W0_h  : g_W0_f;

    const int tid  = threadIdx.x;
    const int cg   = blockIdx.x;              // hidden units [cg*32, cg*32+32)
    const int row0 = blockIdx.y * 128;

    // ---- stage B (96 gate cols of packed words) ----
    for (int i = tid; i < 96*32; i += 256) {
        int c = i >> 5, f = (i & 31) << 2;
        int gcol = ((c >> 5) << 7) + (cg << 5) + (c & 31);
        *(float4*)(sB + c*SB_STRIDE + f) = *(const float4*)(Bw + gcol*128 + f);
    }
    // ---- stage hold slice ----
    for (int i = tid; i < 128*32; i += 256) {
        int r = i >> 5, c = i & 31;
        sAh[r*33 + c] = hin[(size_t)(row0+r)*HID + (cg<<5) + c];
    }
    if (tid < 96) {
        int gcol = ((tid >> 5) << 7) + (cg << 5) + (tid & 31);
        sbih[tid] = bih[gcol]; sbhh[tid] = bhh[gcol]; sW0[tid] = W0[gcol];
#pragma unroll
        for (int k = 0; k < NF; k++) sWx[tid*NF + k] = Wx[gcol*NF + k];
    }
    if (tid >= 96 && tid < 128) sfcw[tid-96] = fcw[(cg<<5) + (tid-96)];
    if (tid < 128) {
        int row = row0 + tid;
        if (NF == 1) {
            int b = row / NNODE, n = row - b*NNODE;
            sX[tid] = pm25[((size_t)b*TH + t)*NNODE + n];
        } else {
#pragma unroll
            for (int k = 0; k < 9; k++) sX[tid*9 + k] = g_x2[(size_t)row*9 + k];
        }
        if (xn_mode == 1) {
            float s = fcb[0];
#pragma unroll
            for (int c2 = 0; c2 < 4; c2++) s += g_xnpart[c2*M_ROWS + row];
            sxn[tid] = s;
        } else if (xn_mode == 2) {
            sxn[tid] = g_xn[row];
        }
    }
    __syncthreads();

    const int lane = tid & 31, w = tid >> 5;
    const int g = lane >> 2, q = lane & 3;
    const int rbase = (w << 4) + g;

    float acc[48];
#pragma unroll
    for (int i = 0; i < 48; i++) acc[i] = 0.0f;

    const float* pA0 = hin + (size_t)(row0 + rbase)*HID + q;
    const float* pA1 = pA0 + 8*HID;

    float an[4];
    an[0] = pA0[0]; an[1] = pA1[0]; an[2] = pA0[4]; an[3] = pA1[4];

#pragma unroll
    for (int kt = 0; kt < 16; kt++) {
        unsigned aw[4];
        aw[0] = pack_hl(an[0]); aw[1] = pack_hl(an[1]);
        aw[2] = pack_hl(an[2]); aw[3] = pack_hl(an[3]);
        if (kt < 15) {
            an[0] = pA0[(kt+1)*8];     an[1] = pA1[(kt+1)*8];
            an[2] = pA0[(kt+1)*8 + 4]; an[3] = pA1[(kt+1)*8 + 4];
        }
        const float* pb = sB + g*SB_STRIDE + kt*8 + 2*q;
#pragma unroll
        for (int jn = 0; jn < 12; jn++) {
            uint2 wb = *(const uint2*)(pb + jn*8*SB_STRIDE);
            unsigned bh0 = __byte_perm(wb.x, wb.x, 0x1010);  // (hi,hi)
            unsigned bh1 = __byte_perm(wb.y, wb.y, 0x1010);
            unsigned bl0 = __byte_perm(wb.x, 0,    0x4432);  // (lo, 0)
            unsigned bl1 = __byte_perm(wb.y, 0,    0x4432);
            mma_bf16(acc + jn*4, aw, bh0, bh1);   // a_hi*b_hi + a_lo*b_hi
            mma_bf16(acc + jn*4, aw, bl0, bl1);   // a_hi*b_lo
        }
    }

    // ---- epilogue: gates + h update + fc partials ----
    float p0 = 0.0f, p1 = 0.0f;
#pragma unroll
    for (int jn4 = 0; jn4 < 4; jn4++) {
#pragma unroll
        for (int e = 0; e < 2; e++) {
            int j = jn4*8 + 2*q + e;           // hidden unit within cg block
            float w0r = sW0[j], w0z = sW0[32+j], w0n = sW0[64+j];
            float bir = sbih[j], biz = sbih[32+j], bin = sbih[64+j];
            float bhr = sbhh[j], bhz = sbhh[32+j], bhn = sbhh[64+j];
            float fwj = sfcw[j];
#pragma unroll
            for (int rs = 0; rs < 2; rs++) {
                int rib = rbase + rs*8;
                int d   = rs*2 + e;
                float xnv = (xn_mode == 0) ? 0.0f : sxn[rib];
                float gir = bir + xnv*w0r;
                float giz = biz + xnv*w0z;
                float gin = bin + xnv*w0n;
#pragma unroll
                for (int k = 0; k < NF; k++) {
                    float xk = (NF == 1) ? sX[rib] : sX[rib*9 + k];
                    gir = fmaf(xk, sWx[j*NF + k],      gir);
                    giz = fmaf(xk, sWx[(32+j)*NF + k], giz);
                    gin = fmaf(xk, sWx[(64+j)*NF + k], gin);
                }
                float rr = sigf(gir + acc[ jn4   *4 + d] + bhr);
                float zz = sigf(giz + acc[(4+jn4)*4 + d] + bhz);
                float nn = tanhfast(gin + rr*(acc[(8+jn4)*4 + d] + bhn));
                float hold = sAh[rib*33 + j];
                float hnew = (1.0f - zz)*nn + zz*hold;
                hout[(size_t)(row0 + rib)*HID + (cg<<5) + j] = hnew;
                float c = hnew * fwj;
                if (rs == 0) p0 += c; else p1 += c;
            }
        }
    }
    // reduce partials over q (lanes g*4+q) and store
    p0 += __shfl_xor_sync(0xffffffffu, p0, 1);
    p0 += __shfl_xor_sync(0xffffffffu, p0, 2);
    p1 += __shfl_xor_sync(0xffffffffu, p1, 1);
    p1 += __shfl_xor_sync(0xffffffffu, p1, 2);
    if (q == 0) {
        g_xnpart[cg*M_ROWS + row0 + rbase]     = p0;
        g_xnpart[cg*M_ROWS + row0 + rbase + 8] = p1;
    }
}

// ---------------- graph: xn (from partials) + wind-gated ChebConv gate -> g_x2 ------
__global__ __launch_bounds__(256) void graph_kernel(int t,
        const float* __restrict__ feature, const float* __restrict__ adj,
        const float* __restrict__ cw0, const float* __restrict__ cw1,
        const float* __restrict__ cb, const float* __restrict__ fcb,
        float* __restrict__ out) {
    int b   = blockIdx.x;
    int tid = threadIdx.x;
    __shared__ float sx[NNODE][9];
    __shared__ float sdinv[NNODE];
    __shared__ float shneg[NNODE];
    __shared__ unsigned int sM[NNODE][6];

    const float* fb = feature + (((size_t)b*(TH+TF) + TH + t)*NNODE)*8;
    for (int i = tid; i < NNODE; i += 256) {
#pragma unroll
        for (int c = 0; c < 8; c++) sx[i][1+c] = fb[i*8 + c];
        int row = b*NNODE + i;
        float s = fcb[0] + g_xnpart[row] + g_xnpart[M_ROWS + row]
                + g_xnpart[2*M_ROWS + row] + g_xnpart[3*M_ROWS + row];
        sx[i][0] = s;
        g_xn[row] = s;
        if (t > 0) out[((size_t)b*TF + (t-1))*NNODE + i] = s;
    }
    __syncthreads();

    // pass 1: per-source-node edge bitmask + degree
    for (int i = tid; i < NNODE; i += 256) {
        float u = sx[i][1];
        float v = sx[i][2];
        const float* c1 = g_comp1 + i*NNODE;
        const float* c2 = g_comp2 + i*NNODE;
        const float* ar = adj     + i*NNODE;
        int deg = 0;
        for (int qq = 0; qq < 6; qq++) {
            unsigned bits = 0;
            int jend = (qq == 5) ? (NNODE - 160) : 32;
            for (int jj = 0; jj < jend; jj++) {
                int j = qq*32 + jj;
                float w = u*c1[j] + v*c2[j];
                if (w >= 0.5f && ar[j] > 0.0f) { deg++; bits |= (1u << jj); }
            }
            sM[i][qq] = bits;
        }
        sdinv[i] = (deg > 0) ? (1.0f / sqrtf((float)deg)) : 0.0f;
        shneg[i] = (deg > 0) ? 0.0f : -1.0f;
    }
    __syncthreads();

    // pass 2: ChebConv y, gate g, write g_x2 = [f0..f7, g]
    for (int j = tid; j < NNODE; j += 256) {
        float y[9];
#pragma unroll
        for (int c = 0; c < 9; c++) y[c] = 0.0f;
        int qq = j >> 5, sh = j & 31;
        for (int i = 0; i < NNODE; i++) {
            float w = ((sM[i][qq] >> sh) & 1u) ? sdinv[i] : 0.0f;
#pragma unroll
            for (int c = 0; c < 9; c++) y[c] = fmaf(w, sx[i][c], y[c]);
        }
        float dj = sdinv[j], hn = shneg[j];
        float acc = cb[0];
#pragma unroll
        for (int c = 0; c < 9; c++) {
            float yc = fmaf(-dj, y[c], hn*sx[j][c]);
            acc += sx[j][c]*cw0[c] + yc*cw1[c];
        }
        float gte = sigf(acc);
        float* o = g_x2 + (size_t)(b*NNODE + j)*9;
#pragma unroll
        for (int c = 0; c < 8; c++) o[c] = sx[j][1+c];
        o[8] = gte;
    }
}

// ---------------- final prediction (t = TF-1) from last partials ----------------
__global__ __launch_bounds__(256) void pred_kernel(const float* __restrict__ fcb,
                                                   float* __restrict__ out) {
    int row = blockIdx.x*256 + threadIdx.x;
    float s = fcb[0] + g_xnpart[row] + g_xnpart[M_ROWS + row]
            + g_xnpart[2*M_ROWS + row] + g_xnpart[3*M_ROWS + row];
    int b = row / NNODE, n = row - b*NNODE;
    out[((size_t)b*TF + (TF-1))*NNODE + n] = s;
}

// ---------------- launch ----------------
extern "C" void kernel_launch(void* const* d_in, const int* in_sizes, int n_in,
                              void* d_out, int out_size) {
    const float* feature   = (const float*)d_in[0];
    const float* pm25      = (const float*)d_in[1];
    const float* adj       = (const float*)d_in[2];
    const float* angles    = (const float*)d_in[3];
    const float* W_ih_hist = (const float*)d_in[4];
    const float* W_hh_hist = (const float*)d_in[5];
    const float* b_ih_hist = (const float*)d_in[6];
    const float* b_hh_hist = (const float*)d_in[7];
    const float* fc_hist_w = (const float*)d_in[8];
    const float* fc_hist_b = (const float*)d_in[9];
    const float* cheb_w0   = (const float*)d_in[10];
    const float* cheb_w1   = (const float*)d_in[11];
    const float* cheb_b    = (const float*)d_in[12];
    const float* W_ih      = (const float*)d_in[13];
    const float* W_hh      = (const float*)d_in[14];
    const float* b_ih      = (const float*)d_in[15];
    const float* b_hh      = (const float*)d_in[16];
    const float* fc_out_w  = (const float*)d_in[17];
    const float* fc_out_b  = (const float*)d_in[18];
    float* out = (float*)d_out;

    cudaFuncSetAttribute(fused_step<1>, cudaFuncAttributeMaxDynamicSharedMemorySize, SMEM_BYTES);
    cudaFuncSetAttribute(fused_step<9>, cudaFuncAttributeMaxDynamicSharedMemorySize, SMEM_BYTES);

    prep_kernel<<<(GCOLS*HID + 255)/256, 256>>>(angles, W_hh_hist, W_hh,
                                                W_ih_hist, b_ih_hist, b_hh_hist,
                                                W_ih, b_ih, b_hh);
    zero_kernel<<<(M_ROWS*HID + 255)/256, 256>>>();

    dim3 fgrid(4, M_ROWS/128);   // (4, 368)

    for (int t = 0; t < TH; t++) {
        fused_step<1><<<fgrid, 256, SMEM_BYTES>>>(t & 1, t, (t == 0) ? 0 : 1,
                                                  pm25, fc_hist_w, fc_hist_b);
    }
    for (int t = 0; t < TF; t++) {
        int s = TH + t;
        graph_kernel<<<BATCH, 256>>>(t, feature, adj, cheb_w0, cheb_w1, cheb_b,
                                     (t == 0) ? fc_hist_b : fc_out_b, out);
        fused_step<9><<<fgrid, 256, SMEM_BYTES>>>(s & 1, t, 2,
                                                  pm25, fc_out_w, fc_out_b);
    }
    pred_kernel<<<M_ROWS/256, 256>>>(fc_out_b, out);
}

// round 10
// speedup vs baseline: 1.8298x; 1.0740x over previous
#include <cuda_runtime.h>
#include <math.h>

#define BATCH 256
#define NNODE 184
#define HID   128
#define TH    24
#define TF    24
#define M_ROWS (BATCH*NNODE)      /* 47104 = 368*128 */
#define GCOLS  (3*HID)            /* 384 */

// ---------------- persistent device scratch ----------------
__device__ float g_hA[(size_t)M_ROWS*HID];
__device__ float g_hB[(size_t)M_ROWS*HID];
__device__ float g_xn[M_ROWS];
__device__ float g_xnpart[4*M_ROWS];             // per-colgroup fc partial sums
__device__ float g_x2[(size_t)M_ROWS*9];         // fore GRU input feats [f0..f7, g]
__device__ float g_comp1[NNODE*NNODE];
__device__ float g_comp2[NNODE*NNODE];
// Whh packed as bf16 (lo<<16 | hi) words, [gatecol][k] with k permuted so that
// within each 8-k chunk, real k r<4 -> slot 2r, r>=4 -> slot 2(r-4)+1 (makes the
// (q, q+4) fragment pair adjacent -> one LDS.64 covering both b regs).
__device__ float g_Bh[GCOLS*HID];
__device__ float g_Bf[GCOLS*HID];
__device__ float g_bih_h[GCOLS], g_bhh_h[GCOLS], g_W0_h[GCOLS], g_Wx_h[GCOLS];
__device__ float g_bih_f[GCOLS], g_bhh_f[GCOLS], g_W0_f[GCOLS], g_Wx_f[GCOLS*9];

__device__ __forceinline__ float sigf(float x)   { return 1.0f/(1.0f + __expf(-x)); }
__device__ __forceinline__ float tanhfast(float x){ return 2.0f/(1.0f + __expf(-2.0f*x)) - 1.0f; }

// pack x into (high16 = bf16(x - bf16(x)), low16 = bf16(x))  == (lo<<16 | hi)
__device__ __forceinline__ unsigned pack_hl(float x) {
    unsigned h2; asm("cvt.rn.bf16x2.f32 %0, %1, %1;" : "=r"(h2) : "f"(x));
    float hif = __uint_as_float(h2 << 16);
    float lo  = x - hif;
    unsigned w; asm("cvt.rn.bf16x2.f32 %0, %1, %2;" : "=r"(w) : "f"(lo), "f"(x));
    return w;
}
// split x into aHH=(bf16(x),bf16(x)) and aL0=(0, bf16(x - bf16(x)))
__device__ __forceinline__ void split_a(float x, unsigned& hh, unsigned& l0) {
    asm("cvt.rn.bf16x2.f32 %0, %1, %1;" : "=r"(hh) : "f"(x));
    float hif = __uint_as_float(hh << 16);
    float lo  = x - hif;
    asm("cvt.rn.bf16x2.f32 %0, %1, %2;" : "=r"(l0) : "f"(0.0f), "f"(lo));
}

__device__ __forceinline__ void mma_bf16(float* d, const unsigned* a, unsigned b0, unsigned b1) {
    asm volatile("mma.sync.aligned.m16n8k16.row.col.f32.bf16.bf16.f32 "
        "{%0,%1,%2,%3}, {%4,%5,%6,%7}, {%8,%9}, {%0,%1,%2,%3};"
        : "+f"(d[0]), "+f"(d[1]), "+f"(d[2]), "+f"(d[3])
        : "r"(a[0]), "r"(a[1]), "r"(a[2]), "r"(a[3]), "r"(b0), "r"(b1));
}

// ---------------- prep ----------------
__global__ void prep_kernel(const float* __restrict__ angles,
                            const float* __restrict__ Whh_h, const float* __restrict__ Whh_f,
                            const float* __restrict__ Wih_h, const float* __restrict__ bih_h,
                            const float* __restrict__ bhh_h,
                            const float* __restrict__ Wih_f, const float* __restrict__ bih_f,
                            const float* __restrict__ bhh_f) {
    int i = blockIdx.x*blockDim.x + threadIdx.x;
    if (i < NNODE*NNODE) {
        float a = angles[i];
        g_comp1[i] = cosf(a);
        g_comp2[i] = cosf(a - 1.57079632679489662f);
    }
    if (i < GCOLS*HID) {
        int gc = i >> 7, k = i & 127;
        int kt = k >> 3, r = k & 7;
        int pos = kt*8 + ((r < 4) ? 2*r : 2*(r-4)+1);
        g_Bh[gc*128 + pos] = __uint_as_float(pack_hl(Whh_h[i]));
        g_Bf[gc*128 + pos] = __uint_as_float(pack_hl(Whh_f[i]));
    }
    if (i < GCOLS) {
        g_bih_h[i] = bih_h[i]; g_bhh_h[i] = bhh_h[i];
        g_W0_h[i]  = Wih_h[i*2]; g_Wx_h[i] = Wih_h[i*2+1];
        g_bih_f[i] = bih_f[i]; g_bhh_f[i] = bhh_f[i];
        g_W0_f[i]  = Wih_f[i*10];
        for (int k = 0; k < 9; k++) g_Wx_f[i*9+k] = Wih_f[i*10+1+k];
    }
}

__global__ void zero_kernel() {
    int i = blockIdx.x*blockDim.x + threadIdx.x;
    if (i < M_ROWS*HID) g_hA[i] = 0.0f;
}

// ---------------- fused step: G = h@Whh^T (bf16-split mma) + GRU gates ----------------
// Grid (4 col-groups, 368 row-groups), 256 threads = 8 warps; warp = 16 rows x 96 cols.
// Block tile: 128 rows x 96 gate cols (= 32 hidden units x {r,z,n}).
#define SB_STRIDE 136
#define SMEM_FLOATS (96*SB_STRIDE + 128*9 + 96*9 + 96*3 + 128 + 32)
#define SMEM_BYTES  (SMEM_FLOATS*4)

template<int NF>
__global__ __launch_bounds__(256, 3) void fused_step(int par, int t, int xn_mode,
        const float* __restrict__ pm25,
        const float* __restrict__ fcw, const float* __restrict__ fcb) {
    extern __shared__ float sm[];
    float* sB   = sm;                    // [96][136] packed bf16x2 words
    float* sX   = sB  + 96*SB_STRIDE;    // [128][<=9] input feats
    float* sWx  = sX  + 128*9;           // [96][<=9]
    float* sW0  = sWx + 96*9;            // [96]
    float* sbih = sW0 + 96;
    float* sbhh = sbih + 96;
    float* sxn  = sbhh + 96;             // [128]
    float* sfcw = sxn + 128;             // [32]

    const float* hin  = par ? g_hB : g_hA;
    float*       hout = par ? g_hA : g_hB;
    const float* Bw  = (NF==1) ? g_Bh   : g_Bf;
    const float* bih = (NF==1) ? g_bih_h : g_bih_f;
    const float* bhh = (NF==1) ? g_bhh_h : g_bhh_f;
    const float* Wx  = (NF==1) ? g_Wx_h  : g_Wx_f;
    const float* W0  = (NF==1) ? g_W0_h  : g_W0_f;

    const int tid  = threadIdx.x;
    const int cg   = blockIdx.x;              // hidden units [cg*32, cg*32+32)
    const int row0 = blockIdx.y * 128;

    // ---- stage B (96 gate cols of packed words) ----
    for (int i = tid; i < 96*32; i += 256) {
        int c = i >> 5, f = (i & 31) << 2;
        int gcol = ((c >> 5) << 7) + (cg << 5) + (c & 31);
        *(float4*)(sB + c*SB_STRIDE + f) = *(const float4*)(Bw + gcol*128 + f);
    }
    if (tid < 96) {
        int gcol = ((tid >> 5) << 7) + (cg << 5) + (tid & 31);
        sbih[tid] = bih[gcol]; sbhh[tid] = bhh[gcol]; sW0[tid] = W0[gcol];
#pragma unroll
        for (int k = 0; k < NF; k++) sWx[tid*NF + k] = Wx[gcol*NF + k];
    }
    if (tid >= 96 && tid < 128) sfcw[tid-96] = fcw[(cg<<5) + (tid-96)];
    if (tid < 128) {
        int row = row0 + tid;
        if (NF == 1) {
            int b = row / NNODE, n = row - b*NNODE;
            sX[tid] = pm25[((size_t)b*TH + t)*NNODE + n];
        } else {
#pragma unroll
            for (int k = 0; k < 9; k++) sX[tid*9 + k] = g_x2[(size_t)row*9 + k];
        }
        if (xn_mode == 1) {
            float s = fcb[0];
#pragma unroll
            for (int c2 = 0; c2 < 4; c2++) s += g_xnpart[c2*M_ROWS + row];
            sxn[tid] = s;
        } else if (xn_mode == 2) {
            sxn[tid] = g_xn[row];
        }
    }
    __syncthreads();

    const int lane = tid & 31, w = tid >> 5;
    const int g = lane >> 2, q = lane & 3;
    const int rbase = (w << 4) + g;

    float acc[48];
#pragma unroll
    for (int i = 0; i < 48; i++) acc[i] = 0.0f;

    const float* pA0 = hin + (size_t)(row0 + rbase)*HID + q;
    const float* pA1 = pA0 + 8*HID;

    float an[4];
    an[0] = pA0[0]; an[1] = pA1[0]; an[2] = pA0[4]; an[3] = pA1[4];

#pragma unroll
    for (int kt = 0; kt < 16; kt++) {
        unsigned aHH[4], aL0[4];
        split_a(an[0], aHH[0], aL0[0]);
        split_a(an[1], aHH[1], aL0[1]);
        split_a(an[2], aHH[2], aL0[2]);
        split_a(an[3], aHH[3], aL0[3]);
        if (kt < 15) {
            an[0] = pA0[(kt+1)*8];     an[1] = pA1[(kt+1)*8];
            an[2] = pA0[(kt+1)*8 + 4]; an[3] = pA1[(kt+1)*8 + 4];
        }
        const float* pb = sB + g*SB_STRIDE + kt*8 + 2*q;
#pragma unroll
        for (int jn = 0; jn < 12; jn++) {
            uint2 wb = *(const uint2*)(pb + jn*8*SB_STRIDE);
            mma_bf16(acc + jn*4, aHH, wb.x, wb.y);   // a_hi*b_hi + a_hi*b_lo
            mma_bf16(acc + jn*4, aL0, wb.x, wb.y);   // a_lo*b_hi
        }
    }

    // ---- preload hold values (this block's 32 hidden units) from global ----
    float2 hold2[4][2];
#pragma unroll
    for (int jn4 = 0; jn4 < 4; jn4++)
#pragma unroll
        for (int rs = 0; rs < 2; rs++)
            hold2[jn4][rs] = *(const float2*)(hin + (size_t)(row0 + rbase + rs*8)*HID
                                              + (cg<<5) + jn4*8 + 2*q);

    // ---- epilogue: gates + h update + fc partials ----
    float p0 = 0.0f, p1 = 0.0f;
#pragma unroll
    for (int jn4 = 0; jn4 < 4; jn4++) {
#pragma unroll
        for (int e = 0; e < 2; e++) {
            int j = jn4*8 + 2*q + e;           // hidden unit within cg block
            float w0r = sW0[j], w0z = sW0[32+j], w0n = sW0[64+j];
            float bir = sbih[j], biz = sbih[32+j], bin = sbih[64+j];
            float bhr = sbhh[j], bhz = sbhh[32+j], bhn = sbhh[64+j];
            float fwj = sfcw[j];
#pragma unroll
            for (int rs = 0; rs < 2; rs++) {
                int rib = rbase + rs*8;
                int d   = rs*2 + e;
                float xnv = (xn_mode == 0) ? 0.0f : sxn[rib];
                float gir = bir + xnv*w0r;
                float giz = biz + xnv*w0z;
                float gin = bin + xnv*w0n;
#pragma unroll
                for (int k = 0; k < NF; k++) {
                    float xk = (NF == 1) ? sX[rib] : sX[rib*9 + k];
                    gir = fmaf(xk, sWx[j*NF + k],      gir);
                    giz = fmaf(xk, sWx[(32+j)*NF + k], giz);
                    gin = fmaf(xk, sWx[(64+j)*NF + k], gin);
                }
                float rr = sigf(gir + acc[ jn4   *4 + d] + bhr);
                float zz = sigf(giz + acc[(4+jn4)*4 + d] + bhz);
                float nn = tanhfast(gin + rr*(acc[(8+jn4)*4 + d] + bhn));
                float hold = (e == 0) ? hold2[jn4][rs].x : hold2[jn4][rs].y;
                float hnew = (1.0f - zz)*nn + zz*hold;
                hout[(size_t)(row0 + rib)*HID + (cg<<5) + j] = hnew;
                float c = hnew * fwj;
                if (rs == 0) p0 += c; else p1 += c;
            }
        }
    }
    // reduce partials over q (lanes g*4+q) and store
    p0 += __shfl_xor_sync(0xffffffffu, p0, 1);
    p0 += __shfl_xor_sync(0xffffffffu, p0, 2);
    p1 += __shfl_xor_sync(0xffffffffu, p1, 1);
    p1 += __shfl_xor_sync(0xffffffffu, p1, 2);
    if (q == 0) {
        g_xnpart[cg*M_ROWS + row0 + rbase]     = p0;
        g_xnpart[cg*M_ROWS + row0 + rbase + 8] = p1;
    }
}

// ---------------- graph: xn (from partials) + wind-gated ChebConv gate -> g_x2 ------
__global__ __launch_bounds__(256) void graph_kernel(int t,
        const float* __restrict__ feature, const float* __restrict__ adj,
        const float* __restrict__ cw0, const float* __restrict__ cw1,
        const float* __restrict__ cb, const float* __restrict__ fcb,
        float* __restrict__ out) {
    int b   = blockIdx.x;
    int tid = threadIdx.x;
    __shared__ float sx[NNODE][9];
    __shared__ float sdinv[NNODE];
    __shared__ float shneg[NNODE];
    __shared__ unsigned int sM[NNODE][6];

    const float* fb = feature + (((size_t)b*(TH+TF) + TH + t)*NNODE)*8;
    for (int i = tid; i < NNODE; i += 256) {
#pragma unroll
        for (int c = 0; c < 8; c++) sx[i][1+c] = fb[i*8 + c];
        int row = b*NNODE + i;
        float s = fcb[0] + g_xnpart[row] + g_xnpart[M_ROWS + row]
                + g_xnpart[2*M_ROWS + row] + g_xnpart[3*M_ROWS + row];
        sx[i][0] = s;
        g_xn[row] = s;
        if (t > 0) out[((size_t)b*TF + (t-1))*NNODE + i] = s;
    }
    __syncthreads();

    // pass 1: per-source-node edge bitmask + degree
    for (int i = tid; i < NNODE; i += 256) {
        float u = sx[i][1];
        float v = sx[i][2];
        const float* c1 = g_comp1 + i*NNODE;
        const float* c2 = g_comp2 + i*NNODE;
        const float* ar = adj     + i*NNODE;
        int deg = 0;
        for (int qq = 0; qq < 6; qq++) {
            unsigned bits = 0;
            int jend = (qq == 5) ? (NNODE - 160) : 32;
            for (int jj = 0; jj < jend; jj++) {
                int j = qq*32 + jj;
                float w = u*c1[j] + v*c2[j];
                if (w >= 0.5f && ar[j] > 0.0f) { deg++; bits |= (1u << jj); }
            }
            sM[i][qq] = bits;
        }
        sdinv[i] = (deg > 0) ? (1.0f / sqrtf((float)deg)) : 0.0f;
        shneg[i] = (deg > 0) ? 0.0f : -1.0f;
    }
    __syncthreads();

    // pass 2: ChebConv y, gate g, write g_x2 = [f0..f7, g]
    for (int j = tid; j < NNODE; j += 256) {
        float y[9];
#pragma unroll
        for (int c = 0; c < 9; c++) y[c] = 0.0f;
        int qq = j >> 5, sh = j & 31;
        for (int i = 0; i < NNODE; i++) {
            float w = ((sM[i][qq] >> sh) & 1u) ? sdinv[i] : 0.0f;
#pragma unroll
            for (int c = 0; c < 9; c++) y[c] = fmaf(w, sx[i][c], y[c]);
        }
        float dj = sdinv[j], hn = shneg[j];
        float acc = cb[0];
#pragma unroll
        for (int c = 0; c < 9; c++) {
            float yc = fmaf(-dj, y[c], hn*sx[j][c]);
            acc += sx[j][c]*cw0[c] + yc*cw1[c];
        }
        float gte = sigf(acc);
        float* o = g_x2 + (size_t)(b*NNODE + j)*9;
#pragma unroll
        for (int c = 0; c < 8; c++) o[c] = sx[j][1+c];
        o[8] = gte;
    }
}

// ---------------- final prediction (t = TF-1) from last partials ----------------
__global__ __launch_bounds__(256) void pred_kernel(const float* __restrict__ fcb,
                                                   float* __restrict__ out) {
    int row = blockIdx.x*256 + threadIdx.x;
    float s = fcb[0] + g_xnpart[row] + g_xnpart[M_ROWS + row]
            + g_xnpart[2*M_ROWS + row] + g_xnpart[3*M_ROWS + row];
    int b = row / NNODE, n = row - b*NNODE;
    out[((size_t)b*TF + (TF-1))*NNODE + n] = s;
}

// ---------------- launch ----------------
extern "C" void kernel_launch(void* const* d_in, const int* in_sizes, int n_in,
                              void* d_out, int out_size) {
    const float* feature   = (const float*)d_in[0];
    const float* pm25      = (const float*)d_in[1];
    const float* adj       = (const float*)d_in[2];
    const float* angles    = (const float*)d_in[3];
    const float* W_ih_hist = (const float*)d_in[4];
    const float* W_hh_hist = (const float*)d_in[5];
    const float* b_ih_hist = (const float*)d_in[6];
    const float* b_hh_hist = (const float*)d_in[7];
    const float* fc_hist_w = (const float*)d_in[8];
    const float* fc_hist_b = (const float*)d_in[9];
    const float* cheb_w0   = (const float*)d_in[10];
    const float* cheb_w1   = (const float*)d_in[11];
    const float* cheb_b    = (const float*)d_in[12];
    const float* W_ih      = (const float*)d_in[13];
    const float* W_hh      = (const float*)d_in[14];
    const float* b_ih      = (const float*)d_in[15];
    const float* b_hh      = (const float*)d_in[16];
    const float* fc_out_w  = (const float*)d_in[17];
    const float* fc_out_b  = (const float*)d_in[18];
    float* out = (float*)d_out;

    cudaFuncSetAttribute(fused_step<1>, cudaFuncAttributeMaxDynamicSharedMemorySize, SMEM_BYTES);
    cudaFuncSetAttribute(fused_step<9>, cudaFuncAttributeMaxDynamicSharedMemorySize, SMEM_BYTES);

    prep_kernel<<<(GCOLS*HID + 255)/256, 256>>>(angles, W_hh_hist, W_hh,
                                                W_ih_hist, b_ih_hist, b_hh_hist,
                                                W_ih, b_ih, b_hh);
    zero_kernel<<<(M_ROWS*HID + 255)/256, 256>>>();

    dim3 fgrid(4, M_ROWS/128);   // (4, 368)

    for (int t = 0; t < TH; t++) {
        fused_step<1><<<fgrid, 256, SMEM_BYTES>>>(t & 1, t, (t == 0) ? 0 : 1,
                                                  pm25, fc_hist_w, fc_hist_b);
    }
    for (int t = 0; t < TF; t++) {
        int s = TH + t;
        graph_kernel<<<BATCH, 256>>>(t, feature, adj, cheb_w0, cheb_w1, cheb_b,
                                     (t == 0) ? fc_hist_b : fc_out_b, out);
        fused_step<9><<<fgrid, 256, SMEM_BYTES>>>(s & 1, t, 2,
                                                  pm25, fc_out_w, fc_out_b);
    }
    pred_kernel<<<M_ROWS/256, 256>>>(fc_out_b, out);
}

// round 11
// speedup vs baseline: 1.8881x; 1.0318x over previous
#include <cuda_runtime.h>
#include <math.h>

#define BATCH 256
#define NNODE 184
#define HID   128
#define TH    24
#define TF    24
#define M_ROWS (BATCH*NNODE)      /* 47104 = 368*128 */
#define GCOLS  (3*HID)            /* 384 */

// ---------------- persistent device scratch ----------------
__device__ unsigned g_hpA[(size_t)M_ROWS*HID];   // h packed (lo<<16|hi) bf16
__device__ unsigned g_hpB[(size_t)M_ROWS*HID];
__device__ float g_xn[M_ROWS];
__device__ float g_xnpart[8*M_ROWS];             // per-colgroup fc partial sums
__device__ float g_x2[(size_t)M_ROWS*9];         // fore GRU input feats [f0..f7, g]
__device__ float g_comp1[NNODE*NNODE];
__device__ float g_comp2[NNODE*NNODE];
// Whh packed per gate-col: 8 iters x 4 q x 4 words:
//   [0]=bf16x2(hi_{k+1},hi_k) [1]=bf16x2(hi_{k+9},hi_{k+8})
//   [2]=bf16x2(lo_{k+1},lo_k) [3]=bf16x2(lo_{k+9},lo_{k+8}),  k = it*16+2q
__device__ unsigned g_Bh[GCOLS*HID];
__device__ unsigned g_Bf[GCOLS*HID];
__device__ float g_bih_h[GCOLS], g_bhh_h[GCOLS], g_W0_h[GCOLS], g_Wx_h[GCOLS];
__device__ float g_bih_f[GCOLS], g_bhh_f[GCOLS], g_W0_f[GCOLS], g_Wx_f[GCOLS*9];

__device__ __forceinline__ float sigf(float x)   { return 1.0f/(1.0f + __expf(-x)); }
__device__ __forceinline__ float tanhfast(float x){ return 2.0f/(1.0f + __expf(-2.0f*x)) - 1.0f; }

__device__ __forceinline__ unsigned bf16x2_of(float hi_val, float lo_val) {
    unsigned w; asm("cvt.rn.bf16x2.f32 %0, %1, %2;" : "=r"(w) : "f"(hi_val), "f"(lo_val));
    return w;   // high16 = hi_val, low16 = lo_val
}
__device__ __forceinline__ float bf16_round(float x) {
    unsigned h; asm("cvt.rn.bf16x2.f32 %0, %1, %1;" : "=r"(h) : "f"(x));
    return __uint_as_float(h << 16);
}
// pack x into (high16 = bf16(x - bf16(x)), low16 = bf16(x))
__device__ __forceinline__ unsigned pack_hl(float x) {
    unsigned h2; asm("cvt.rn.bf16x2.f32 %0, %1, %1;" : "=r"(h2) : "f"(x));
    float lo = x - __uint_as_float(h2 << 16);
    unsigned w; asm("cvt.rn.bf16x2.f32 %0, %1, %2;" : "=r"(w) : "f"(lo), "f"(x));
    return w;
}
// reconstruct fp32 ~= hi + lo from packed word
__device__ __forceinline__ float unpack_hl(unsigned w) {
    return __uint_as_float(w << 16) + __uint_as_float(w & 0xFFFF0000u);
}

__device__ __forceinline__ void mma_bf16(float* d, const unsigned* a, unsigned b0, unsigned b1) {
    asm volatile("mma.sync.aligned.m16n8k16.row.col.f32.bf16.bf16.f32 "
        "{%0,%1,%2,%3}, {%4,%5,%6,%7}, {%8,%9}, {%0,%1,%2,%3};"
        : "+f"(d[0]), "+f"(d[1]), "+f"(d[2]), "+f"(d[3])
        : "r"(a[0]), "r"(a[1]), "r"(a[2]), "r"(a[3]), "r"(b0), "r"(b1));
}

// ---------------- prep ----------------
__global__ void prep_kernel(const float* __restrict__ angles,
                            const float* __restrict__ Whh_h, const float* __restrict__ Whh_f,
                            const float* __restrict__ Wih_h, const float* __restrict__ bih_h,
                            const float* __restrict__ bhh_h,
                            const float* __restrict__ Wih_f, const float* __restrict__ bih_f,
                            const float* __restrict__ bhh_f) {
    int i = blockIdx.x*blockDim.x + threadIdx.x;
    if (i < NNODE*NNODE) {
        float a = angles[i];
        g_comp1[i] = cosf(a);
        g_comp2[i] = cosf(a - 1.57079632679489662f);
    }
    if (i < GCOLS*32) {
        int gc = i >> 5, r5 = i & 31;
        int it = r5 >> 2, qq = r5 & 3;
        int k0 = it*16 + qq*2;
        unsigned* dsth = g_Bh + gc*128 + it*16 + qq*4;
        unsigned* dstf = g_Bf + gc*128 + it*16 + qq*4;
        const float* Wh = Whh_h + gc*128;
        const float* Wf = Whh_f + gc*128;
        {
            float w0 = Wh[k0], w1 = Wh[k0+1], w8 = Wh[k0+8], w9 = Wh[k0+9];
            dsth[0] = bf16x2_of(w1, w0);
            dsth[1] = bf16x2_of(w9, w8);
            dsth[2] = bf16x2_of(w1 - bf16_round(w1), w0 - bf16_round(w0));
            dsth[3] = bf16x2_of(w9 - bf16_round(w9), w8 - bf16_round(w8));
        }
        {
            float w0 = Wf[k0], w1 = Wf[k0+1], w8 = Wf[k0+8], w9 = Wf[k0+9];
            dstf[0] = bf16x2_of(w1, w0);
            dstf[1] = bf16x2_of(w9, w8);
            dstf[2] = bf16x2_of(w1 - bf16_round(w1), w0 - bf16_round(w0));
            dstf[3] = bf16x2_of(w9 - bf16_round(w9), w8 - bf16_round(w8));
        }
    }
    if (i < GCOLS) {
        g_bih_h[i] = bih_h[i]; g_bhh_h[i] = bhh_h[i];
        g_W0_h[i]  = Wih_h[i*2]; g_Wx_h[i] = Wih_h[i*2+1];
        g_bih_f[i] = bih_f[i]; g_bhh_f[i] = bhh_f[i];
        g_W0_f[i]  = Wih_f[i*10];
        for (int k = 0; k < 9; k++) g_Wx_f[i*9+k] = Wih_f[i*10+1+k];
    }
}

__global__ void zero_kernel() {
    int i = blockIdx.x*blockDim.x + threadIdx.x;
    if (i < M_ROWS*HID) g_hpA[i] = 0u;
}

// ---------------- fused step: G = h@Whh^T (3-MMA bf16 split) + GRU gates ----------------
// Grid (8 col-groups, 368 row-groups), 256 threads = 8 warps; warp = 16 rows x 48 cols.
// Block tile: 128 rows x 48 gate cols (= 16 hidden units x {r,z,n}).
#define SB_STRIDE 144
#define SMEM_FLOATS (48*SB_STRIDE + 128*9 + 48*9 + 48*3 + 128 + 16)
#define SMEM_BYTES  (SMEM_FLOATS*4)

template<int NF>
__global__ __launch_bounds__(256, 4) void fused_step(int par, int t, int xn_mode,
        const float* __restrict__ pm25,
        const float* __restrict__ fcw, const float* __restrict__ fcb) {
    extern __shared__ float sm[];
    unsigned* sB = (unsigned*)sm;        // [48][144] packed bf16x2 words
    float* sX   = sm  + 48*SB_STRIDE;    // [128][<=9] input feats
    float* sWx  = sX  + 128*9;           // [48][<=9]
    float* sW0  = sWx + 48*9;            // [48]
    float* sbih = sW0 + 48;
    float* sbhh = sbih + 48;
    float* sxn  = sbhh + 48;             // [128]
    float* sfcw = sxn + 128;             // [16]

    const unsigned* hin  = par ? g_hpB : g_hpA;
    unsigned*       hout = par ? g_hpA : g_hpB;
    const unsigned* Bw = (NF==1) ? g_Bh : g_Bf;
    const float* bih = (NF==1) ? g_bih_h : g_bih_f;
    const float* bhh = (NF==1) ? g_bhh_h : g_bhh_f;
    const float* Wx  = (NF==1) ? g_Wx_h  : g_Wx_f;
    const float* W0  = (NF==1) ? g_W0_h  : g_W0_f;

    const int tid  = threadIdx.x;
    const int cg   = blockIdx.x;              // hidden units [cg*16, cg*16+16)
    const int row0 = blockIdx.y * 128;

    // ---- stage B: 48 gate cols (p in {r,z,n} x 16 local hu) ----
    for (int i = tid; i < 48*32; i += 256) {
        int c = i >> 5, f = (i & 31) << 2;
        int gcol = ((c >> 4) << 7) + (cg << 4) + (c & 15);
        *(uint4*)(sB + c*SB_STRIDE + f) = *(const uint4*)(Bw + gcol*128 + f);
    }
    if (tid < 48) {
        int gcol = ((tid >> 4) << 7) + (cg << 4) + (tid & 15);
        sbih[tid] = bih[gcol]; sbhh[tid] = bhh[gcol]; sW0[tid] = W0[gcol];
#pragma unroll
        for (int k = 0; k < NF; k++) sWx[tid*NF + k] = Wx[gcol*NF + k];
    }
    if (tid >= 48 && tid < 64) sfcw[tid-48] = fcw[(cg<<4) + (tid-48)];
    if (tid < 128) {
        int row = row0 + tid;
        if (NF == 1) {
            int b = row / NNODE, n = row - b*NNODE;
            sX[tid] = pm25[((size_t)b*TH + t)*NNODE + n];
        } else {
#pragma unroll
            for (int k = 0; k < 9; k++) sX[tid*9 + k] = g_x2[(size_t)row*9 + k];
        }
        if (xn_mode == 1) {
            float s = fcb[0];
#pragma unroll
            for (int c2 = 0; c2 < 8; c2++) s += g_xnpart[c2*M_ROWS + row];
            sxn[tid] = s;
        } else if (xn_mode == 2) {
            sxn[tid] = g_xn[row];
        }
    }
    __syncthreads();

    const int lane = tid & 31, w = tid >> 5;
    const int g = lane >> 2, q = lane & 3;
    const int rbase = (w << 4) + g;

    float acc[24];
#pragma unroll
    for (int i = 0; i < 24; i++) acc[i] = 0.0f;

    const unsigned* hpR0 = hin + (size_t)(row0 + rbase)*HID;
    const unsigned* hpR1 = hpR0 + 8*HID;

#pragma unroll
    for (int it = 0; it < 8; it++) {
        // A fragments for real k in [16*it, 16*it+16)
        uint2 u0 = *(const uint2*)(hpR0 + it*16 + 2*q);
        uint2 u1 = *(const uint2*)(hpR0 + it*16 + 2*q + 8);
        uint2 v0 = *(const uint2*)(hpR1 + it*16 + 2*q);
        uint2 v1 = *(const uint2*)(hpR1 + it*16 + 2*q + 8);
        unsigned aH[4], aL[4];
        aH[0] = __byte_perm(u0.x, u0.y, 0x5410);  // (hi_k, hi_{k+1})
        aL[0] = __byte_perm(u0.x, u0.y, 0x7632);  // (lo_k, lo_{k+1})
        aH[1] = __byte_perm(v0.x, v0.y, 0x5410);
        aL[1] = __byte_perm(v0.x, v0.y, 0x7632);
        aH[2] = __byte_perm(u1.x, u1.y, 0x5410);
        aL[2] = __byte_perm(u1.x, u1.y, 0x7632);
        aH[3] = __byte_perm(v1.x, v1.y, 0x5410);
        aL[3] = __byte_perm(v1.x, v1.y, 0x7632);
        const unsigned* pb = sB + g*SB_STRIDE + it*16 + 4*q;
#pragma unroll
        for (int jn = 0; jn < 6; jn++) {
            uint4 bw = *(const uint4*)(pb + jn*8*SB_STRIDE);
            mma_bf16(acc + jn*4, aH, bw.x, bw.y);   // hi*hi
            mma_bf16(acc + jn*4, aL, bw.x, bw.y);   // lo*hi
            mma_bf16(acc + jn*4, aH, bw.z, bw.w);   // hi*lo
        }
    }

    // ---- epilogue: gates + h update + fc partials ----
    float p0 = 0.0f, p1 = 0.0f;
#pragma unroll
    for (int jj = 0; jj < 2; jj++) {
        // hold words (packed) for this thread's hu pair (e=0,1), rows rbase, rbase+8
        uint2 hw0 = *(const uint2*)(hin + (size_t)(row0 + rbase    )*HID + (cg<<4) + jj*8 + 2*q);
        uint2 hw1 = *(const uint2*)(hin + (size_t)(row0 + rbase + 8)*HID + (cg<<4) + jj*8 + 2*q);
        unsigned outw[2][2];
#pragma unroll
        for (int e = 0; e < 2; e++) {
            int l = jj*8 + 2*q + e;            // local hu in [0,16)
            float w0r = sW0[l], w0z = sW0[16+l], w0n = sW0[32+l];
            float bir = sbih[l], biz = sbih[16+l], bin = sbih[32+l];
            float bhr = sbhh[l], bhz = sbhh[16+l], bhn = sbhh[32+l];
            float fwj = sfcw[l];
#pragma unroll
            for (int rs = 0; rs < 2; rs++) {
                int rib = rbase + rs*8;
                int d   = rs*2 + e;
                float xnv = (xn_mode == 0) ? 0.0f : sxn[rib];
                float gir = bir + xnv*w0r;
                float giz = biz + xnv*w0z;
                float gin = bin + xnv*w0n;
#pragma unroll
                for (int k = 0; k < NF; k++) {
                    float xk = (NF == 1) ? sX[rib] : sX[rib*9 + k];
                    gir = fmaf(xk, sWx[l*NF + k],      gir);
                    giz = fmaf(xk, sWx[(16+l)*NF + k], giz);
                    gin = fmaf(xk, sWx[(32+l)*NF + k], gin);
                }
                float rr = sigf(gir + acc[ jj   *4 + d] + bhr);
                float zz = sigf(giz + acc[(2+jj)*4 + d] + bhz);
                float nn = tanhfast(gin + rr*(acc[(4+jj)*4 + d] + bhn));
                unsigned hwv = (rs == 0) ? ((e == 0) ? hw0.x : hw0.y)
                                         : ((e == 0) ? hw1.x : hw1.y);
                float hold = unpack_hl(hwv);
                float hnew = (1.0f - zz)*nn + zz*hold;
                outw[rs][e] = pack_hl(hnew);
                float c = hnew * fwj;
                if (rs == 0) p0 += c; else p1 += c;
            }
        }
        *(uint2*)(hout + (size_t)(row0 + rbase    )*HID + (cg<<4) + jj*8 + 2*q)
            = make_uint2(outw[0][0], outw[0][1]);
        *(uint2*)(hout + (size_t)(row0 + rbase + 8)*HID + (cg<<4) + jj*8 + 2*q)
            = make_uint2(outw[1][0], outw[1][1]);
    }
    // reduce partials over q (lanes g*4+q) and store
    p0 += __shfl_xor_sync(0xffffffffu, p0, 1);
    p0 += __shfl_xor_sync(0xffffffffu, p0, 2);
    p1 += __shfl_xor_sync(0xffffffffu, p1, 1);
    p1 += __shfl_xor_sync(0xffffffffu, p1, 2);
    if (q == 0) {
        g_xnpart[cg*M_ROWS + row0 + rbase]     = p0;
        g_xnpart[cg*M_ROWS + row0 + rbase + 8] = p1;
    }
}

// ---------------- graph: xn (from partials) + wind-gated ChebConv gate -> g_x2 ------
__global__ __launch_bounds__(256) void graph_kernel(int t,
        const float* __restrict__ feature, const float* __restrict__ adj,
        const float* __restrict__ cw0, const float* __restrict__ cw1,
        const float* __restrict__ cb, const float* __restrict__ fcb,
        float* __restrict__ out) {
    int b   = blockIdx.x;
    int tid = threadIdx.x;
    __shared__ float sx[NNODE][9];
    __shared__ float sdinv[NNODE];
    __shared__ float shneg[NNODE];
    __shared__ unsigned int sM[NNODE][6];

    const float* fb = feature + (((size_t)b*(TH+TF) + TH + t)*NNODE)*8;
    for (int i = tid; i < NNODE; i += 256) {
#pragma unroll
        for (int c = 0; c < 8; c++) sx[i][1+c] = fb[i*8 + c];
        int row = b*NNODE + i;
        float s = fcb[0];
#pragma unroll
        for (int c2 = 0; c2 < 8; c2++) s += g_xnpart[c2*M_ROWS + row];
        sx[i][0] = s;
        g_xn[row] = s;
        if (t > 0) out[((size_t)b*TF + (t-1))*NNODE + i] = s;
    }
    __syncthreads();

    // pass 1: per-source-node edge bitmask + degree
    for (int i = tid; i < NNODE; i += 256) {
        float u = sx[i][1];
        float v = sx[i][2];
        const float* c1 = g_comp1 + i*NNODE;
        const float* c2 = g_comp2 + i*NNODE;
        const float* ar = adj     + i*NNODE;
        int deg = 0;
        for (int qq = 0; qq < 6; qq++) {
            unsigned bits = 0;
            int jend = (qq == 5) ? (NNODE - 160) : 32;
            for (int jj = 0; jj < jend; jj++) {
                int j = qq*32 + jj;
                float w = u*c1[j] + v*c2[j];
                if (w >= 0.5f && ar[j] > 0.0f) { deg++; bits |= (1u << jj); }
            }
            sM[i][qq] = bits;
        }
        sdinv[i] = (deg > 0) ? (1.0f / sqrtf((float)deg)) : 0.0f;
        shneg[i] = (deg > 0) ? 0.0f : -1.0f;
    }
    __syncthreads();

    // pass 2: ChebConv y, gate g, write g_x2 = [f0..f7, g]
    for (int j = tid; j < NNODE; j += 256) {
        float y[9];
#pragma unroll
        for (int c = 0; c < 9; c++) y[c] = 0.0f;
        int qq = j >> 5, sh = j & 31;
        for (int i = 0; i < NNODE; i++) {
            float w = ((sM[i][qq] >> sh) & 1u) ? sdinv[i] : 0.0f;
#pragma unroll
            for (int c = 0; c < 9; c++) y[c] = fmaf(w, sx[i][c], y[c]);
        }
        float dj = sdinv[j], hn = shneg[j];
        float acc = cb[0];
#pragma unroll
        for (int c = 0; c < 9; c++) {
            float yc = fmaf(-dj, y[c], hn*sx[j][c]);
            acc += sx[j][c]*cw0[c] + yc*cw1[c];
        }
        float gte = sigf(acc);
        float* o = g_x2 + (size_t)(b*NNODE + j)*9;
#pragma unroll
        for (int c = 0; c < 8; c++) o[c] = sx[j][1+c];
        o[8] = gte;
    }
}

// ---------------- final prediction (t = TF-1) from last partials ----------------
__global__ __launch_bounds__(256) void pred_kernel(const float* __restrict__ fcb,
                                                   float* __restrict__ out) {
    int row = blockIdx.x*256 + threadIdx.x;
    float s = fcb[0];
#pragma unroll
    for (int c2 = 0; c2 < 8; c2++) s += g_xnpart[c2*M_ROWS + row];
    int b = row / NNODE, n = row - b*NNODE;
    out[((size_t)b*TF + (TF-1))*NNODE + n] = s;
}

// ---------------- launch ----------------
extern "C" void kernel_launch(void* const* d_in, const int* in_sizes, int n_in,
                              void* d_out, int out_size) {
    const float* feature   = (const float*)d_in[0];
    const float* pm25      = (const float*)d_in[1];
    const float* adj       = (const float*)d_in[2];
    const float* angles    = (const float*)d_in[3];
    const float* W_ih_hist = (const float*)d_in[4];
    const float* W_hh_hist = (const float*)d_in[5];
    const float* b_ih_hist = (const float*)d_in[6];
    const float* b_hh_hist = (const float*)d_in[7];
    const float* fc_hist_w = (const float*)d_in[8];
    const float* fc_hist_b = (const float*)d_in[9];
    const float* cheb_w0   = (const float*)d_in[10];
    const float* cheb_w1   = (const float*)d_in[11];
    const float* cheb_b    = (const float*)d_in[12];
    const float* W_ih      = (const float*)d_in[13];
    const float* W_hh      = (const float*)d_in[14];
    const float* b_ih      = (const float*)d_in[15];
    const float* b_hh      = (const float*)d_in[16];
    const float* fc_out_w  = (const float*)d_in[17];
    const float* fc_out_b  = (const float*)d_in[18];
    float* out = (float*)d_out;

    cudaFuncSetAttribute(fused_step<1>, cudaFuncAttributeMaxDynamicSharedMemorySize, SMEM_BYTES);
    cudaFuncSetAttribute(fused_step<9>, cudaFuncAttributeMaxDynamicSharedMemorySize, SMEM_BYTES);

    prep_kernel<<<(NNODE*NNODE + 255)/256, 256>>>(angles, W_hh_hist, W_hh,
                                                  W_ih_hist, b_ih_hist, b_hh_hist,
                                                  W_ih, b_ih, b_hh);
    zero_kernel<<<(M_ROWS*HID + 255)/256, 256>>>();

    dim3 fgrid(8, M_ROWS/128);   // (8, 368)

    for (int t = 0; t < TH; t++) {
        fused_step<1><<<fgrid, 256, SMEM_BYTES>>>(t & 1, t, (t == 0) ? 0 : 1,
                                                  pm25, fc_hist_w, fc_hist_b);
    }
    for (int t = 0; t < TF; t++) {
        int s = TH + t;
        graph_kernel<<<BATCH, 256>>>(t, feature, adj, cheb_w0, cheb_w1, cheb_b,
                                     (t == 0) ? fc_hist_b : fc_out_b, out);
        fused_step<9><<<fgrid, 256, SMEM_BYTES>>>(s & 1, t, 2,
                                                  pm25, fc_out_w, fc_out_b);
    }
    pred_kernel<<<M_ROWS/256, 256>>>(fc_out_b, out);
}